// round 1
// baseline (speedup 1.0000x reference)
#include <cuda_runtime.h>
#include <math.h>

// ---------------------------------------------------------------------------
// YOLOv2 head: 1x1 convs (GEMM) -> decode -> per-class greedy NMS
// Problem sizes
#define FMP     40
#define HW      1600          // 40*40 cells
#define BPC     5
#define NBOX    8000          // HW * BPC
#define NCLS    80
#define KDIM    512
#define MCOLS   432           // padded row stride of outmat (425 cols used)
#define CONF_TH 0.3f
#define NMS_TH  0.5f

// Output layout in d_out (float32, 56000 elems):
//   [0,32000)      bboxes [8000,4]
//   [32000,40000)  score
//   [40000,48000)  labels (as float)
//   [48000,56000)  keep (0/1 as float)
#define OUT_SCORE  32000
#define OUT_LABEL  40000
#define OUT_KEEP   48000

__constant__ float c_anchor_w[5] = {17.f, 55.f, 92.f, 202.f, 289.f};
__constant__ float c_anchor_h[5] = {25.f, 75.f, 206.f, 21.f, 311.f};

// Scratch (device globals; no allocation allowed)
__device__ float g_outmat[HW * MCOLS];     // [cell, col]: col 0..399 cls, 400..404 obj, 405..424 reg
__device__ float g_b2[NBOX * 4];           // re-interpreted boxes used for IoU
__device__ float g_score[NBOX];
__device__ int   g_cls_count[NCLS];
__device__ int   g_cls_list[NCLS * NBOX];

__device__ __forceinline__ float sigmoidf_(float x) {
    return 1.f / (1.f + expf(-x));
}

// ---------------------------------------------------------------------------
__global__ void zero_counts_kernel() {
    int t = threadIdx.x;
    if (t < NCLS) g_cls_count[t] = 0;
}

// ---------------------------------------------------------------------------
// GEMM: cls logits.  out[cell, m] = sum_k W[m,k] * F[k,cell] + bias[m]
// W = w_cls [400,512] row-major, F = cls_feat [512,1600] row-major.
// Grid: (25 n-tiles, 7 m-tiles), 256 threads. BM=BN=64, BK=16.
__global__ void gemm_cls_kernel(const float* __restrict__ W,
                                const float* __restrict__ bias,
                                const float* __restrict__ F) {
    __shared__ float sA[16][68];   // [k][m]
    __shared__ float sB[16][68];   // [k][n]

    const int m0 = blockIdx.y * 64;
    const int n0 = blockIdx.x * 64;
    const int tid = threadIdx.x;          // 0..255
    const int tx = tid & 15;              // n-group
    const int ty = tid >> 4;              // m-group

    float acc[4][4];
#pragma unroll
    for (int i = 0; i < 4; i++)
#pragma unroll
        for (int j = 0; j < 4; j++) acc[i][j] = 0.f;

    for (int k0 = 0; k0 < KDIM; k0 += 16) {
        // load A tile 64x16 (1024 elems, 4 per thread)
#pragma unroll
        for (int it = 0; it < 4; it++) {
            int e = tid + it * 256;
            int k = e & 15, m = e >> 4;
            float v = 0.f;
            int gm = m0 + m;
            if (gm < 400) v = W[gm * KDIM + k0 + k];
            sA[k][m] = v;
        }
        // load B tile 16x64 (1024 elems, 4 per thread)
#pragma unroll
        for (int it = 0; it < 4; it++) {
            int e = tid + it * 256;
            int n = e & 63, k = e >> 6;
            sB[k][n] = F[(k0 + k) * HW + n0 + n];
        }
        __syncthreads();

#pragma unroll
        for (int k = 0; k < 16; k++) {
            float a_[4], b_[4];
#pragma unroll
            for (int i = 0; i < 4; i++) a_[i] = sA[k][ty * 4 + i];
#pragma unroll
            for (int j = 0; j < 4; j++) b_[j] = sB[k][tx * 4 + j];
#pragma unroll
            for (int i = 0; i < 4; i++)
#pragma unroll
                for (int j = 0; j < 4; j++) acc[i][j] = fmaf(a_[i], b_[j], acc[i][j]);
        }
        __syncthreads();
    }

#pragma unroll
    for (int i = 0; i < 4; i++) {
        int m = m0 + ty * 4 + i;
        if (m >= 400) continue;
        float bv = bias[m];
#pragma unroll
        for (int j = 0; j < 4; j++) {
            int n = n0 + tx * 4 + j;
            g_outmat[n * MCOLS + m] = acc[i][j] + bv;
        }
    }
}

// ---------------------------------------------------------------------------
// GEMM: obj (5 rows) + reg (20 rows), both from reg_feat. M=25.
// out col = 400 + r; r in [0,5) obj, [5,25) reg.
// Grid: 25 n-tiles of 64 cells, 256 threads.
__global__ void gemm_reg_kernel(const float* __restrict__ Wobj,
                                const float* __restrict__ Bobj,
                                const float* __restrict__ Wreg,
                                const float* __restrict__ Breg,
                                const float* __restrict__ F) {
    __shared__ float sB[32][66];    // [k][n]
    __shared__ float sW[32][26];    // [k][r]

    const int n0 = blockIdx.x * 64;
    const int tid = threadIdx.x;
    const int n  = tid & 63;
    const int rs = tid >> 6;        // 0..3

    float acc[7];
#pragma unroll
    for (int i = 0; i < 7; i++) acc[i] = 0.f;

    for (int k0 = 0; k0 < KDIM; k0 += 32) {
        // F tile: 32x64 = 2048 elems, 8 per thread
#pragma unroll
        for (int it = 0; it < 8; it++) {
            int e = tid + it * 256;
            int kk = e >> 6, nn = e & 63;
            sB[kk][nn] = F[(k0 + kk) * HW + n0 + nn];
        }
        // W tile: 32x25 = 800 elems
        for (int e = tid; e < 800; e += 256) {
            int kk = e / 25, r = e % 25;
            float v = (r < 5) ? Wobj[r * KDIM + k0 + kk]
                              : Wreg[(r - 5) * KDIM + k0 + kk];
            sW[kk][r] = v;
        }
        __syncthreads();

#pragma unroll
        for (int kk = 0; kk < 32; kk++) {
            float fb = sB[kk][n];
#pragma unroll
            for (int i = 0; i < 7; i++) {
                int r = rs + i * 4;
                if (r < 25) acc[i] = fmaf(sW[kk][r], fb, acc[i]);
            }
        }
        __syncthreads();
    }

#pragma unroll
    for (int i = 0; i < 7; i++) {
        int r = rs + i * 4;
        if (r < 25) {
            float bv = (r < 5) ? Bobj[r] : Breg[r - 5];
            g_outmat[(n0 + n) * MCOLS + 400 + r] = acc[i] + bv;
        }
    }
}

// ---------------------------------------------------------------------------
// Per-box decode: argmax class, score, box decode, b2 boxes, class bucketing.
__global__ void box_kernel(float* __restrict__ dout) {
    int i = blockIdx.x * blockDim.x + threadIdx.x;
    if (i >= NBOX) return;
    int cell = i / BPC;
    int a    = i % BPC;
    const float* row = g_outmat + cell * MCOLS;

    // argmax over 80 cls logits (first-max semantics)
    const float* cl = row + a * NCLS;
    float best = cl[0];
    int bi = 0;
#pragma unroll 4
    for (int c = 1; c < NCLS; c++) {
        float v = cl[c];
        if (v > best) { best = v; bi = c; }
    }

    float obj   = row[400 + a];
    float score = sqrtf(sigmoidf_(obj) * sigmoidf_(best));

    float tx = row[405 + a * 4 + 0];
    float ty = row[405 + a * 4 + 1];
    float tw = row[405 + a * 4 + 2];
    float th = row[405 + a * 4 + 3];

    float ax = (float)(cell % FMP);
    float ay = (float)(cell / FMP);
    float cx = (sigmoidf_(tx) + ax) * 32.f;
    float cy = (sigmoidf_(ty) + ay) * 32.f;
    float w  = expf(tw) * c_anchor_w[a];
    float h  = expf(th) * c_anchor_h[a];

    float x1 = cx - 0.5f * w, y1 = cy - 0.5f * h;
    float x2 = cx + 0.5f * w, y2 = cy + 0.5f * h;

    dout[i * 4 + 0] = x1;
    dout[i * 4 + 1] = y1;
    dout[i * 4 + 2] = x2;
    dout[i * 4 + 3] = y2;
    dout[OUT_SCORE + i] = score;
    dout[OUT_LABEL + i] = (float)bi;

    // b2: re-interpret (x1,y1,x2,y2) as (cx,cy,w,h)
    g_b2[i * 4 + 0] = x1 - 0.5f * x2;
    g_b2[i * 4 + 1] = y1 - 0.5f * y2;
    g_b2[i * 4 + 2] = x1 + 0.5f * x2;
    g_b2[i * 4 + 3] = y1 + 0.5f * y2;
    g_score[i] = score;

    int slot = atomicAdd(&g_cls_count[bi], 1);
    g_cls_list[bi * NBOX + slot] = i;
}

// ---------------------------------------------------------------------------
// Per-class sort (score desc, index asc) + greedy NMS. One block per class.
// Dynamic smem layout (cap n = 8000):
//   [0,32000)        float ls[]   load-order scores
//   [32000,64000)    int   lg[]   load-order global box idx
//   [64000,96000)    int   si[]   sorted global idx
//   [96000,128000)   float ss[]   sorted scores
//   [128000,136000)  uchar supp[]
#define NMS_SMEM 136000
__global__ void nms_kernel(float* __restrict__ dout) {
    extern __shared__ char smem[];
    float* s_ls = (float*)smem;
    int*   s_lg = (int*)(smem + 32000);
    int*   s_si = (int*)(smem + 64000);
    float* s_ss = (float*)(smem + 96000);
    unsigned char* s_supp = (unsigned char*)(smem + 128000);

    const int c = blockIdx.x;
    const int n = g_cls_count[c];
    const int* list = g_cls_list + c * NBOX;
    const int tid = threadIdx.x;

    for (int t = tid; t < n; t += blockDim.x) {
        int gi = list[t];
        s_lg[t] = gi;
        s_ls[t] = g_score[gi];
    }
    __syncthreads();

    // rank by (score desc, global idx asc) -> deterministic, matches stable sort
    for (int t = tid; t < n; t += blockDim.x) {
        float st = s_ls[t];
        int   gt = s_lg[t];
        int r = 0;
        for (int j = 0; j < n; j++) {
            float sj = s_ls[j];
            r += (sj > st) || (sj == st && s_lg[j] < gt);
        }
        s_si[r] = gt;
        s_ss[r] = st;
    }
    for (int t = tid; t < n; t += blockDim.x) s_supp[t] = 0;
    __syncthreads();

    // greedy sequential scan; intra-step parallel suppression
    for (int k = 0; k < n; k++) {
        // uniform predicate across block (all read same shared values)
        if (!s_supp[k] && s_ss[k] >= CONF_TH) {
            int gk = s_si[k];
            float bx1 = g_b2[gk * 4 + 0];
            float by1 = g_b2[gk * 4 + 1];
            float bx2 = g_b2[gk * 4 + 2];
            float by2 = g_b2[gk * 4 + 3];
            float ak = (bx2 - bx1) * (by2 - by1);
            for (int j = k + 1 + tid; j < n; j += blockDim.x) {
                if (s_supp[j]) continue;
                int gj = s_si[j];
                float cx1 = g_b2[gj * 4 + 0];
                float cy1 = g_b2[gj * 4 + 1];
                float cx2 = g_b2[gj * 4 + 2];
                float cy2 = g_b2[gj * 4 + 3];
                float xx1 = fmaxf(bx1, cx1);
                float yy1 = fmaxf(by1, cy1);
                float xx2 = fminf(bx2, cx2);
                float yy2 = fminf(by2, cy2);
                float inter = fmaxf(1e-10f, xx2 - xx1) * fmaxf(1e-10f, yy2 - yy1);
                float aj = (cx2 - cx1) * (cy2 - cy1);
                float iou = inter / (ak + aj - inter + 1e-14f);
                if (iou > NMS_TH) s_supp[j] = 1;
            }
        }
        __syncthreads();
    }

    for (int t = tid; t < n; t += blockDim.x) {
        float kv = (s_ss[t] >= CONF_TH && !s_supp[t]) ? 1.f : 0.f;
        dout[OUT_KEEP + s_si[t]] = kv;
    }
}

// ---------------------------------------------------------------------------
extern "C" void kernel_launch(void* const* d_in, const int* in_sizes, int n_in,
                              void* d_out, int out_size) {
    const float* cls_feat = (const float*)d_in[0];  // [1,512,40,40]
    const float* reg_feat = (const float*)d_in[1];  // [1,512,40,40]
    const float* w_obj    = (const float*)d_in[2];  // [5,512]
    const float* b_obj    = (const float*)d_in[3];  // [5]
    const float* w_cls    = (const float*)d_in[4];  // [400,512]
    const float* b_cls    = (const float*)d_in[5];  // [400]
    const float* w_reg    = (const float*)d_in[6];  // [20,512]
    const float* b_reg    = (const float*)d_in[7];  // [20]
    float* out = (float*)d_out;

    cudaFuncSetAttribute(nms_kernel, cudaFuncAttributeMaxDynamicSharedMemorySize, NMS_SMEM);

    zero_counts_kernel<<<1, 128>>>();
    gemm_cls_kernel<<<dim3(25, 7), 256>>>(w_cls, b_cls, cls_feat);
    gemm_reg_kernel<<<25, 256>>>(w_obj, b_obj, w_reg, b_reg, reg_feat);
    box_kernel<<<(NBOX + 255) / 256, 256>>>(out);
    nms_kernel<<<NCLS, 256, NMS_SMEM>>>(out);
}

// round 2
// speedup vs baseline: 1.7823x; 1.7823x over previous
#include <cuda_runtime.h>
#include <math.h>

// ---------------------------------------------------------------------------
#define FMP     40
#define HW      1600
#define BPC     5
#define NBOX    8000
#define NCLS    80
#define KDIM    512
#define MCOLS   432
#define CONF_TH 0.3f
#define NMS_TH  0.5f

#define OUT_SCORE  32000
#define OUT_LABEL  40000
#define OUT_KEEP   48000

__constant__ float c_anchor_w[5] = {17.f, 55.f, 92.f, 202.f, 289.f};
__constant__ float c_anchor_h[5] = {25.f, 75.f, 206.f, 21.f, 311.f};

__device__ float g_outmat[HW * MCOLS];   // [cell][col]: 0..399 cls, 400..404 obj, 405..424 reg, 425..431 pad
__device__ float g_b2[NBOX * 4];
__device__ float g_score[NBOX];
__device__ int   g_cls_count[NCLS];
__device__ int   g_cls_list[NCLS * NBOX];

typedef unsigned long long ull;

__device__ __forceinline__ ull dup2(float a) {
    ull r; asm("mov.b64 %0, {%1, %1};" : "=l"(r) : "f"(a)); return r;
}
__device__ __forceinline__ void ffma2(ull& d, ull a, ull b) {
    asm("fma.rn.f32x2 %0, %1, %2, %0;" : "+l"(d) : "l"(a), "l"(b));
}
__device__ __forceinline__ float2 unpk(ull v) {
    float2 f; asm("mov.b64 {%0, %1}, %2;" : "=f"(f.x), "=f"(f.y) : "l"(v)); return f;
}
__device__ __forceinline__ float sigmoidf_(float x) { return 1.f / (1.f + expf(-x)); }

// ---------------------------------------------------------------------------
// Fused GEMM (fp32x2 packed FFMA): out[n][m] = sum_k W[m][k]*F[k][n] + bias[m]
// Grid: (13 n-tiles of 128, 8 m-tiles of 64). m-tiles 0..6: w_cls/cls_feat.
// m-tile 7: obj+reg rows (25 used) from reg_feat. 128 threads, thread 8m x 8n.
__global__ __launch_bounds__(128) void gemm_kernel(
    const float* __restrict__ cls_feat, const float* __restrict__ reg_feat,
    const float* __restrict__ w_obj, const float* __restrict__ b_obj,
    const float* __restrict__ w_cls, const float* __restrict__ b_cls,
    const float* __restrict__ w_reg, const float* __restrict__ b_reg)
{
    __shared__ float sA[2][16][64];     // [buf][k][m]
    __shared__ float sB[2][16][128];    // [buf][k][n]

    const int bx = blockIdx.x;          // n-tile
    const int by = blockIdx.y;          // m-tile
    const int tid = threadIdx.x;
    const int tx = tid & 15;            // n-group (8n each)
    const int ty = tid >> 4;            // m-group (8m each)
    const int n0 = bx * 128;

    // fold class-counter zeroing into this kernel (runs before box_kernel)
    if (by == 7 && bx == 0 && tid < NCLS) g_cls_count[tid] = 0;

    const float* F = (by < 7) ? cls_feat : reg_feat;

    // A-load job: each thread loads 8 consecutive k of one weight row
    const int am = tid >> 1;             // 0..63 (m within tile)
    const int ak = (tid & 1) * 8;        // 0 or 8
    const float* aptr = nullptr;
    if (by < 7) {
        int gm = by * 64 + am;
        if (gm < 400) aptr = w_cls + gm * KDIM;
    } else {
        if (am < 5)       aptr = w_obj + am * KDIM;
        else if (am < 25) aptr = w_reg + (am - 5) * KDIM;
    }

    float4 ra0, ra1, rb[4];

    auto load_ab = [&](int k0) {
        if (aptr) {
            ra0 = *(const float4*)(aptr + k0 + ak);
            ra1 = *(const float4*)(aptr + k0 + ak + 4);
        } else {
            ra0 = make_float4(0.f, 0.f, 0.f, 0.f); ra1 = ra0;
        }
#pragma unroll
        for (int t = 0; t < 4; t++) {
            int f = tid + t * 128;
            int kk = f >> 5, nf = f & 31;
            int n = n0 + nf * 4;
            if (n < HW) rb[t] = *(const float4*)(F + (k0 + kk) * HW + n);
            else        rb[t] = make_float4(0.f, 0.f, 0.f, 0.f);
        }
    };
    auto store_ab = [&](int p) {
        sA[p][ak + 0][am] = ra0.x; sA[p][ak + 1][am] = ra0.y;
        sA[p][ak + 2][am] = ra0.z; sA[p][ak + 3][am] = ra0.w;
        sA[p][ak + 4][am] = ra1.x; sA[p][ak + 5][am] = ra1.y;
        sA[p][ak + 6][am] = ra1.z; sA[p][ak + 7][am] = ra1.w;
#pragma unroll
        for (int t = 0; t < 4; t++) {
            int f = tid + t * 128;
            int kk = f >> 5, nf = f & 31;
            *(float4*)&sB[p][kk][nf * 4] = rb[t];
        }
    };

    ull acc[8][4];
#pragma unroll
    for (int i = 0; i < 8; i++)
#pragma unroll
        for (int j = 0; j < 4; j++) acc[i][j] = 0ULL;

    load_ab(0);
    store_ab(0);
    __syncthreads();
    int p = 0;
    for (int kb = 1; kb <= 32; kb++) {
        if (kb < 32) load_ab(kb * 16);
#pragma unroll
        for (int k = 0; k < 16; k++) {
            float4 a0 = *(const float4*)&sA[p][k][ty * 8];
            float4 a1 = *(const float4*)&sA[p][k][ty * 8 + 4];
            ulonglong2 bb0 = *(const ulonglong2*)&sB[p][k][tx * 8];
            ulonglong2 bb1 = *(const ulonglong2*)&sB[p][k][tx * 8 + 4];
            ull aa[8];
            aa[0] = dup2(a0.x); aa[1] = dup2(a0.y); aa[2] = dup2(a0.z); aa[3] = dup2(a0.w);
            aa[4] = dup2(a1.x); aa[5] = dup2(a1.y); aa[6] = dup2(a1.z); aa[7] = dup2(a1.w);
#pragma unroll
            for (int i = 0; i < 8; i++) {
                ffma2(acc[i][0], aa[i], bb0.x);
                ffma2(acc[i][1], aa[i], bb0.y);
                ffma2(acc[i][2], aa[i], bb1.x);
                ffma2(acc[i][3], aa[i], bb1.y);
            }
        }
        if (kb < 32) { store_ab(p ^ 1); __syncthreads(); p ^= 1; }
    }

    // bias vector for this thread's 8 m-rows
    float bv[8];
#pragma unroll
    for (int i = 0; i < 8; i++) {
        if (by < 7) { int m = by * 64 + ty * 8 + i; bv[i] = (m < 400) ? b_cls[m] : 0.f; }
        else { int r = ty * 8 + i; bv[i] = (r < 5) ? b_obj[r] : (r < 25 ? b_reg[r - 5] : 0.f); }
    }
    bool mvalid = true;
    if (by == 6 && ty >= 2) mvalid = false;   // m 400..447 of cls tile: invalid
    if (by == 7 && ty >= 4) mvalid = false;   // r >= 32: would overflow padding
    const int mcol0 = (by < 7) ? by * 64 + ty * 8 : 400 + ty * 8; // r 25..31 land in pad cols

    if (mvalid) {
#pragma unroll
        for (int jp = 0; jp < 4; jp++) {
            float2 c[8];
#pragma unroll
            for (int i = 0; i < 8; i++) c[i] = unpk(acc[i][jp]);
            int n = n0 + tx * 8 + jp * 2;
            if (n < HW) {
                float* dst = g_outmat + n * MCOLS + mcol0;
                *(float4*)dst       = make_float4(c[0].x + bv[0], c[1].x + bv[1], c[2].x + bv[2], c[3].x + bv[3]);
                *(float4*)(dst + 4) = make_float4(c[4].x + bv[4], c[5].x + bv[5], c[6].x + bv[6], c[7].x + bv[7]);
            }
            if (n + 1 < HW) {
                float* dst = g_outmat + (n + 1) * MCOLS + mcol0;
                *(float4*)dst       = make_float4(c[0].y + bv[0], c[1].y + bv[1], c[2].y + bv[2], c[3].y + bv[3]);
                *(float4*)(dst + 4) = make_float4(c[4].y + bv[4], c[5].y + bv[5], c[6].y + bv[6], c[7].y + bv[7]);
            }
        }
    }
}

// ---------------------------------------------------------------------------
// Decode: 4 threads per box. Each scans 20 classes (5x float4), shfl-reduce.
__global__ __launch_bounds__(256) void box_kernel(float* __restrict__ dout) {
    int t = blockIdx.x * 256 + threadIdx.x;   // 32000 threads exactly
    int i = t >> 2;                           // box id
    int q = t & 3;                            // quarter
    int cell = i / BPC;
    int a    = i - cell * BPC;
    const float* row = g_outmat + cell * MCOLS;
    const float* cl  = row + a * NCLS + q * 20;

    float best = -1e30f; int bi = 0;
#pragma unroll
    for (int v = 0; v < 5; v++) {
        float4 f = *(const float4*)(cl + v * 4);
        int c0 = q * 20 + v * 4;
        if (f.x > best) { best = f.x; bi = c0; }
        if (f.y > best) { best = f.y; bi = c0 + 1; }
        if (f.z > best) { best = f.z; bi = c0 + 2; }
        if (f.w > best) { best = f.w; bi = c0 + 3; }
    }
#pragma unroll
    for (int off = 1; off < 4; off <<= 1) {
        float ov = __shfl_xor_sync(0xffffffffu, best, off);
        int   oi = __shfl_xor_sync(0xffffffffu, bi, off);
        if (ov > best || (ov == best && oi < bi)) { best = ov; bi = oi; }
    }
    if (q != 0) return;

    float obj   = row[400 + a];
    float score = sqrtf(sigmoidf_(obj) * sigmoidf_(best));

    float txv = row[405 + a * 4 + 0];
    float tyv = row[405 + a * 4 + 1];
    float twv = row[405 + a * 4 + 2];
    float thv = row[405 + a * 4 + 3];

    float ax = (float)(cell % FMP);
    float ay = (float)(cell / FMP);
    float cx = (sigmoidf_(txv) + ax) * 32.f;
    float cy = (sigmoidf_(tyv) + ay) * 32.f;
    float w  = expf(twv) * c_anchor_w[a];
    float h  = expf(thv) * c_anchor_h[a];

    float x1 = cx - 0.5f * w, y1 = cy - 0.5f * h;
    float x2 = cx + 0.5f * w, y2 = cy + 0.5f * h;

    *(float4*)(dout + i * 4) = make_float4(x1, y1, x2, y2);
    dout[OUT_SCORE + i] = score;
    dout[OUT_LABEL + i] = (float)bi;

    *(float4*)(g_b2 + i * 4) = make_float4(x1 - 0.5f * x2, y1 - 0.5f * y2,
                                           x1 + 0.5f * x2, y1 + 0.5f * y2);
    g_score[i] = score;

    int slot = atomicAdd(&g_cls_count[bi], 1);
    g_cls_list[bi * NBOX + slot] = i;
}

// ---------------------------------------------------------------------------
// Per-class NMS. Fast path (n <= 512): rank-sort + IoU bitmatrix + warp greedy.
// Fallback (n > 512): block-sequential greedy over global arrays.
#define NMS_SMEM 136000
#define NMS_CAP  512

__global__ __launch_bounds__(256) void nms_kernel(float* __restrict__ dout) {
    extern __shared__ char smem[];
    const int c = blockIdx.x;
    const int n = g_cls_count[c];
    const int* list = g_cls_list + c * NBOX;
    const int tid = threadIdx.x;

    if (n <= NMS_CAP) {
        int*      s_lg = (int*)smem;                       // [512]
        float*    s_ls = (float*)(smem + 2048);
        int*      s_si = (int*)(smem + 4096);
        float*    s_ss = (float*)(smem + 6144);
        float*    s_x1 = (float*)(smem + 8192);
        float*    s_y1 = (float*)(smem + 10240);
        float*    s_x2 = (float*)(smem + 12288);
        float*    s_y2 = (float*)(smem + 14336);
        float*    s_ar = (float*)(smem + 16384);
        unsigned* s_vb = (unsigned*)(smem + 18432);        // valid bits [16]
        unsigned* s_sw = (unsigned*)(smem + 18496);        // live-out   [16]
        unsigned* s_M  = (unsigned*)(smem + 18560);        // [512*16] bit rows
        const int W = (n + 31) >> 5;

        for (int t = tid; t < n; t += 256) { int gi = list[t]; s_lg[t] = gi; s_ls[t] = g_score[gi]; }
        if (tid < 16) s_vb[tid] = 0u;
        __syncthreads();

        // rank by (score desc, global idx asc): deterministic stable order
        for (int t = tid; t < n; t += 256) {
            float st = s_ls[t]; int gt = s_lg[t]; int r = 0;
            for (int j = 0; j < n; j++) {
                float sj = s_ls[j];
                r += (sj > st) || (sj == st && s_lg[j] < gt);
            }
            s_si[r] = gt; s_ss[r] = st;
            float x1 = g_b2[gt * 4 + 0], y1 = g_b2[gt * 4 + 1];
            float x2 = g_b2[gt * 4 + 2], y2 = g_b2[gt * 4 + 3];
            s_x1[r] = x1; s_y1[r] = y1; s_x2[r] = x2; s_y2[r] = y2;
            s_ar[r] = (x2 - x1) * (y2 - y1);
            if (st >= CONF_TH) atomicOr(&s_vb[r >> 5], 1u << (r & 31));
        }
        __syncthreads();

        // adjacency: M[k] bit j set iff j>k and IoU(k,j) > thresh
        for (int t = tid; t < n * W; t += 256) {
            int k = t / W, w = t - k * W;
            float kx1 = s_x1[k], ky1 = s_y1[k], kx2 = s_x2[k], ky2 = s_y2[k], ka = s_ar[k];
            unsigned bits = 0;
            int jbase = w * 32;
            int jend = min(jbase + 32, n);
            for (int j = max(jbase, k + 1); j < jend; j++) {
                float xx1 = fmaxf(kx1, s_x1[j]);
                float yy1 = fmaxf(ky1, s_y1[j]);
                float xx2 = fminf(kx2, s_x2[j]);
                float yy2 = fminf(ky2, s_y2[j]);
                float inter = fmaxf(1e-10f, xx2 - xx1) * fmaxf(1e-10f, yy2 - yy1);
                float iou = inter / (ka + s_ar[j] - inter + 1e-14f);
                if (iou > NMS_TH) bits |= 1u << (j & 31);
            }
            s_M[k * W + w] = bits;
        }
        __syncthreads();

        // warp-0 greedy: live = valid & ~suppressed; 1 shfl per step
        if (tid < 32) {
            unsigned live = (tid < W) ? s_vb[tid] : 0u;
            for (int k = 0; k < n; k++) {
                unsigned lw = __shfl_sync(0xffffffffu, live, k >> 5);
                if (lw & (1u << (k & 31))) {
                    if (tid < W) live &= ~s_M[k * W + tid];
                }
            }
            if (tid < 16) s_sw[tid] = (tid < W) ? live : 0u;
        }
        __syncthreads();

        for (int t = tid; t < n; t += 256) {
            float kv = ((s_sw[t >> 5] >> (t & 31)) & 1u) ? 1.f : 0.f;
            dout[OUT_KEEP + s_si[t]] = kv;
        }
    } else {
        // --------- fallback: block-sequential greedy (correct for any n) ----
        float* s_ls = (float*)smem;
        int*   s_lg = (int*)(smem + 32000);
        int*   s_si = (int*)(smem + 64000);
        float* s_ss = (float*)(smem + 96000);
        unsigned char* s_supp = (unsigned char*)(smem + 128000);

        for (int t = tid; t < n; t += 256) {
            int gi = list[t];
            s_lg[t] = gi; s_ls[t] = g_score[gi];
        }
        __syncthreads();
        for (int t = tid; t < n; t += 256) {
            float st = s_ls[t]; int gt = s_lg[t]; int r = 0;
            for (int j = 0; j < n; j++) {
                float sj = s_ls[j];
                r += (sj > st) || (sj == st && s_lg[j] < gt);
            }
            s_si[r] = gt; s_ss[r] = st;
        }
        for (int t = tid; t < n; t += 256) s_supp[t] = 0;
        __syncthreads();

        for (int k = 0; k < n; k++) {
            if (!s_supp[k] && s_ss[k] >= CONF_TH) {
                int gk = s_si[k];
                float bx1 = g_b2[gk * 4 + 0], by1 = g_b2[gk * 4 + 1];
                float bx2 = g_b2[gk * 4 + 2], by2 = g_b2[gk * 4 + 3];
                float ak = (bx2 - bx1) * (by2 - by1);
                for (int j = k + 1 + tid; j < n; j += 256) {
                    if (s_supp[j]) continue;
                    int gj = s_si[j];
                    float cx1 = g_b2[gj * 4 + 0], cy1 = g_b2[gj * 4 + 1];
                    float cx2 = g_b2[gj * 4 + 2], cy2 = g_b2[gj * 4 + 3];
                    float xx1 = fmaxf(bx1, cx1);
                    float yy1 = fmaxf(by1, cy1);
                    float xx2 = fminf(bx2, cx2);
                    float yy2 = fminf(by2, cy2);
                    float inter = fmaxf(1e-10f, xx2 - xx1) * fmaxf(1e-10f, yy2 - yy1);
                    float aj = (cx2 - cx1) * (cy2 - cy1);
                    float iou = inter / (ak + aj - inter + 1e-14f);
                    if (iou > NMS_TH) s_supp[j] = 1;
                }
            }
            __syncthreads();
        }
        for (int t = tid; t < n; t += 256) {
            float kv = (s_ss[t] >= CONF_TH && !s_supp[t]) ? 1.f : 0.f;
            dout[OUT_KEEP + s_si[t]] = kv;
        }
    }
}

// ---------------------------------------------------------------------------
extern "C" void kernel_launch(void* const* d_in, const int* in_sizes, int n_in,
                              void* d_out, int out_size) {
    const float* cls_feat = (const float*)d_in[0];
    const float* reg_feat = (const float*)d_in[1];
    const float* w_obj    = (const float*)d_in[2];
    const float* b_obj    = (const float*)d_in[3];
    const float* w_cls    = (const float*)d_in[4];
    const float* b_cls    = (const float*)d_in[5];
    const float* w_reg    = (const float*)d_in[6];
    const float* b_reg    = (const float*)d_in[7];
    float* out = (float*)d_out;

    cudaFuncSetAttribute(nms_kernel, cudaFuncAttributeMaxDynamicSharedMemorySize, NMS_SMEM);

    gemm_kernel<<<dim3(13, 8), 128>>>(cls_feat, reg_feat, w_obj, b_obj,
                                      w_cls, b_cls, w_reg, b_reg);
    box_kernel<<<125, 256>>>(out);
    nms_kernel<<<NCLS, 256, NMS_SMEM>>>(out);
}